// round 9
// baseline (speedup 1.0000x reference)
#include <cuda_runtime.h>
#include <math.h>

static constexpr int V   = 32000;    // vocab (row length)
static constexpr int V4  = V / 4;    // float4 count per row
static constexpr int NT  = 512;      // threads per CTA
static constexpr int NW  = NT / 32;  // warps per CTA

// merge sorted triple (a1>=a2>=a3) into sorted triple (b1>=b2>=b3): top-3 of union
__device__ __forceinline__ void merge3(float& b1, float& b2, float& b3,
                                       float a1, float a2, float a3)
{
    float n1 = fmaxf(b1, a1);
    float n2 = fmaxf(fminf(b1, a1), fmaxf(b2, a2));
    float n3 = fmaxf(fmaxf(b3, a3), fmaxf(fminf(b1, a2), fminf(b2, a1)));
    b1 = n1; b2 = n2; b3 = n3;
}

// insert scalar a into sorted triple (branchless, 5 FMNMX)
__device__ __forceinline__ void insert3(float& q1, float& q2, float& q3, float a)
{
    float t2 = fminf(q1, a);  q1 = fmaxf(q1, a);
    float t3 = fminf(q2, t2); q2 = fmaxf(q2, t2);
    q3 = fmaxf(q3, t3);
}

__global__ void __launch_bounds__(NT, 4)
bisection_loss_kernel(const float* __restrict__ X,
                      const int* __restrict__ target_raw,   // int32 OR int64 (detected)
                      float* __restrict__ out)
{
    __shared__ float r1[NW];
    __shared__ float r2[NW];
    __shared__ float r3[NW];
    __shared__ float sb[4];    // broadcast: tau / M1 / M2 / M3

    const int tid  = threadIdx.x;
    const int lane = tid & 31;
    const int wid  = tid >> 5;
    const long long row = blockIdx.x;

    const float* __restrict__ xrow = X + row * (long long)V;
    const float4* __restrict__ g4  = reinterpret_cast<const float4*>(xrow);

    // ================= Pass 1: HBM stream, MAX-ONLY (4 FMNMX / float4) =======
    float lmax = -INFINITY;
    #pragma unroll 4
    for (int i = tid; i < V4; i += NT) {
        float4 v = __ldg(&g4[i]);
        lmax = fmaxf(lmax, fmaxf(fmaxf(v.x, v.y), fmaxf(v.z, v.w)));
    }

    // warp top-3 of the per-thread maxima
    float w1 = lmax, w2 = -INFINITY, w3 = -INFINITY;
    #pragma unroll
    for (int off = 16; off; off >>= 1) {
        float o1 = __shfl_xor_sync(0xffffffffu, w1, off);
        float o2 = __shfl_xor_sync(0xffffffffu, w2, off);
        float o3 = __shfl_xor_sync(0xffffffffu, w3, off);
        merge3(w1, w2, w3, o1, o2, o3);
    }
    if (lane == 0) { r1[wid] = w1; r2[wid] = w2; r3[wid] = w3; }
    __syncthreads();

    // warp 0 merges the NW triples -> tau = 3rd largest thread-max (<= true M3)
    if (wid == 0) {
        float T1 = -INFINITY, T2 = -INFINITY, T3 = -INFINITY;
        if (lane < NW) { T1 = r1[lane]; T2 = r2[lane]; T3 = r3[lane]; }
        #pragma unroll
        for (int off = 8; off; off >>= 1) {
            float o1 = __shfl_xor_sync(0xffffffffu, T1, off);
            float o2 = __shfl_xor_sync(0xffffffffu, T2, off);
            float o3 = __shfl_xor_sync(0xffffffffu, T3, off);
            merge3(T1, T2, T3, o1, o2, o3);
        }
        if (lane == 0) sb[0] = T3;
    }
    __syncthreads();
    const float tau = sb[0];

    // ================= Pass 2: L2-resident reread, tau-filtered top-3 ========
    // every element >= tau gets inserted; since M1,M2,M3 >= tau, the merged
    // result is the EXACT global top-3, and all copies of M1/M2 are visible
    // to the multiplicity counters below.
    float q1 = -INFINITY, q2 = -INFINITY, q3 = -INFINITY;
    #pragma unroll 4
    for (int i = tid; i < V4; i += NT) {
        float4 v = __ldg(&g4[i]);
        float vm = fmaxf(fmaxf(v.x, v.y), fmaxf(v.z, v.w));
        if (vm >= tau) {               // ~3 float4s per row -> near-zero divergence
            insert3(q1, q2, q3, v.x);
            insert3(q1, q2, q3, v.y);
            insert3(q1, q2, q3, v.z);
            insert3(q1, q2, q3, v.w);
        }
    }
    float u1 = q1, u2 = q2, u3 = q3;
    #pragma unroll
    for (int off = 16; off; off >>= 1) {
        float o1 = __shfl_xor_sync(0xffffffffu, u1, off);
        float o2 = __shfl_xor_sync(0xffffffffu, u2, off);
        float o3 = __shfl_xor_sync(0xffffffffu, u3, off);
        merge3(u1, u2, u3, o1, o2, o3);
    }
    __syncthreads();   // r1..r3 reuse
    if (lane == 0) { r1[wid] = u1; r2[wid] = u2; r3[wid] = u3; }
    __syncthreads();
    if (wid == 0) {
        float T1 = -INFINITY, T2 = -INFINITY, T3 = -INFINITY;
        if (lane < NW) { T1 = r1[lane]; T2 = r2[lane]; T3 = r3[lane]; }
        #pragma unroll
        for (int off = 8; off; off >>= 1) {
            float o1 = __shfl_xor_sync(0xffffffffu, T1, off);
            float o2 = __shfl_xor_sync(0xffffffffu, T2, off);
            float o3 = __shfl_xor_sync(0xffffffffu, T3, off);
            merge3(T1, T2, T3, o1, o2, o3);
        }
        if (lane == 0) { sb[1] = T1; sb[2] = T2; sb[3] = T3; }
    }
    __syncthreads();
    const float M1 = sb[1], M2 = sb[2], M3 = sb[3];

    // multiplicities of M1 / M2 from per-thread slots (conservative: any
    // within-thread hidden copy forces the count away from 1 -> fallback)
    int c1 = __syncthreads_count(q1 == M1) + __syncthreads_count(q2 == M1)
           + __syncthreads_count(q3 == M1);
    int cW = __syncthreads_count(q1 == M2) + __syncthreads_count(q2 == M2)
           + __syncthreads_count(q3 == M2);

    // ================= Bisection (redundant, exact f32 replication) ==========
    const float CEXP = (float)(1.0 / 31999.0);          // inv_exp as f32
    const float M1s = 0.5f * M1;                         // Xs = (alpha-1)*X, exact
    const float M2s = 0.5f * M2;
    const float M3s = 0.5f * M3;
    float tmin = M1s - 1.0f;
    float diff = (M1s - (float)0.005590169943749474) - tmin;  // tmax - tmin
    float t    = tmin;
    if (M1s - M2s < 0.98f) {
        // only-M1-above-t => y < 0.98 => powf(y,c) provably < 1: mask == (M2s > t)
        #pragma unroll 1
        for (int it = 0; it < 50; it++) {
            diff *= 0.5f;
            t = tmin + diff;
            if (M2s > t) tmin = t;
        }
    } else {
        #pragma unroll 1
        for (int it = 0; it < 50; it++) {
            diff *= 0.5f;
            t = tmin + diff;
            if ((M2s > t) || (powf(M1s - t, CEXP) >= 1.0f)) tmin = t;
        }
    }
    const float tf = t;               // final Z uses the LAST iteration's t
    const bool needW = (M2s > tf);

    // closed form provably exact when M1 unique, M2 unique, no 3rd element > tf
    const bool fallback = (c1 != 1) || (cW != 1) || (M3s > tf);

    float S = 0.0f, A = 0.0f, D = 0.0f;
    if (fallback) {
        // ---- rare exact path: full rescan (L2-resident), float4 skip test ----
        const float tf2 = 2.0f * tf;
        float s = 0.0f, a = 0.0f, d = 0.0f;
        #pragma unroll 2
        for (int i = tid; i < V4; i += NT) {
            float4 v = __ldg(&g4[i]);
            float vm = fmaxf(fmaxf(v.x, v.y), fmaxf(v.z, v.w));
            if (vm > tf2) {
                float y;
                y = 0.5f * v.x - tf;
                if (y > 0.0f) { float z = powf(y, CEXP); s += z; a += z * sqrtf(z); d += z * v.x; }
                y = 0.5f * v.y - tf;
                if (y > 0.0f) { float z = powf(y, CEXP); s += z; a += z * sqrtf(z); d += z * v.y; }
                y = 0.5f * v.z - tf;
                if (y > 0.0f) { float z = powf(y, CEXP); s += z; a += z * sqrtf(z); d += z * v.z; }
                y = 0.5f * v.w - tf;
                if (y > 0.0f) { float z = powf(y, CEXP); s += z; a += z * sqrtf(z); d += z * v.w; }
            }
        }
        #pragma unroll
        for (int off = 16; off; off >>= 1) {
            s += __shfl_down_sync(0xffffffffu, s, off);
            a += __shfl_down_sync(0xffffffffu, a, off);
            d += __shfl_down_sync(0xffffffffu, d, off);
        }
        __syncthreads();
        if (lane == 0) { r1[wid] = s; r2[wid] = a; r3[wid] = d; }
        __syncthreads();
        if (tid == 0) {
            #pragma unroll
            for (int w = 0; w < NW; w++) { S += r1[w]; A += r2[w]; D += r3[w]; }
        }
    } else if (tid == 0) {
        // ---- closed form: contributors are exactly {M1} (+ {M2} if needW) ----
        float z1 = powf(M1s - tf, CEXP);
        S = z1; A = z1 * sqrtf(z1); D = z1 * M1;
        if (needW) {
            float z2 = powf(M2s - tf, CEXP);
            S += z2; A += z2 * sqrtf(z2); D += z2 * M2;
        }
    }

    if (tid == 0) {
        // ---- dtype-agnostic target fetch (int32 vs int64 buffer) ----
        // int64 LE with values in [0,32000) => odd 32-bit words are all zero.
        int acc = __ldg(&target_raw[1]) | __ldg(&target_raw[3])
                | __ldg(&target_raw[5]) | __ldg(&target_raw[7])
                | __ldg(&target_raw[9]) | __ldg(&target_raw[11])
                | __ldg(&target_raw[13]) | __ldg(&target_raw[15]);
        int tg = (acc == 0) ? __ldg(&target_raw[2 * (int)row])
                            : __ldg(&target_raw[(int)row]);
        if (tg < 0) tg = 0;
        if (tg >= V) tg = V - 1;   // defensive clamp: never fault

        float xt = __ldg(&xrow[tg]);
        // sum(p^alpha) = A / S^1.5 ; loss = (1 - sumPa)/0.75 + D/S - X[target]
        float sumPa = A / (S * sqrtf(S));
        out[row] = (1.0f - sumPa) / 0.75f + D / S - xt;
    }
}

extern "C" void kernel_launch(void* const* d_in, const int* in_sizes, int n_in,
                              void* d_out, int out_size)
{
    const float* X   = (const float*)d_in[0];
    const int*   tgt = (const int*)d_in[1];
    float*       out = (float*)d_out;
    const int B = out_size;   // 4096 rows

    bisection_loss_kernel<<<B, NT>>>(X, tgt, out);
}

// round 10
// speedup vs baseline: 1.2183x; 1.2183x over previous
#include <cuda_runtime.h>
#include <math.h>

static constexpr int V   = 32000;    // vocab (row length)
static constexpr int V4  = V / 4;    // float4 count per row
static constexpr int NT  = 512;      // threads per CTA
static constexpr int NW  = NT / 32;  // warps per CTA

// merge sorted triple (a1>=a2>=a3) into sorted triple (b1>=b2>=b3): top-3 of union
__device__ __forceinline__ void merge3(float& b1, float& b2, float& b3,
                                       float a1, float a2, float a3)
{
    float n1 = fmaxf(b1, a1);
    float n2 = fmaxf(fminf(b1, a1), fmaxf(b2, a2));
    float n3 = fmaxf(fmaxf(b3, a3), fmaxf(fminf(b1, a2), fminf(b2, a1)));
    b1 = n1; b2 = n2; b3 = n3;
}

__global__ void __launch_bounds__(NT, 4)
bisection_loss_kernel(const float* __restrict__ X,
                      const int* __restrict__ target_raw,   // int32 OR int64 (detected)
                      float* __restrict__ out)
{
    __shared__ float r1[NW];
    __shared__ float r2[NW];
    __shared__ float r3[NW];
    __shared__ float sb[3];    // broadcast M1 / M2 / M3

    const int tid  = threadIdx.x;
    const int lane = tid & 31;
    const int wid  = tid >> 5;
    const long long row = blockIdx.x;

    const float* __restrict__ xrow = X + row * (long long)V;
    const float4* __restrict__ g4  = reinterpret_cast<const float4*>(xrow);

    // ---- Single pass: per-thread TOP-2 (branchless, 3 FMNMX/elem) ----
    float p1 = -INFINITY, p2 = -INFINITY;
    #pragma unroll 4
    for (int i = tid; i < V4; i += NT) {
        float4 v = __ldg(&g4[i]);
        float t2;
        t2 = fminf(p1, v.x); p1 = fmaxf(p1, v.x); p2 = fmaxf(p2, t2);
        t2 = fminf(p1, v.y); p1 = fmaxf(p1, v.y); p2 = fmaxf(p2, t2);
        t2 = fminf(p1, v.z); p1 = fmaxf(p1, v.z); p2 = fmaxf(p2, t2);
        t2 = fminf(p1, v.w); p1 = fmaxf(p1, v.w); p2 = fmaxf(p2, t2);
    }

    // ---- merge per-thread PAIRS into a block TOP-3-of-union ----
    // (union of all top-2 pairs contains the true global top-3 unless the
    //  thread owning M1 also owns M2 -> detected below, falls back)
    float w1 = p1, w2 = p2, w3 = -INFINITY;
    #pragma unroll
    for (int off = 16; off; off >>= 1) {
        float o1 = __shfl_xor_sync(0xffffffffu, w1, off);
        float o2 = __shfl_xor_sync(0xffffffffu, w2, off);
        float o3 = __shfl_xor_sync(0xffffffffu, w3, off);
        merge3(w1, w2, w3, o1, o2, o3);
    }
    if (lane == 0) { r1[wid] = w1; r2[wid] = w2; r3[wid] = w3; }
    __syncthreads();
    if (wid == 0) {
        float T1 = -INFINITY, T2 = -INFINITY, T3 = -INFINITY;
        if (lane < NW) { T1 = r1[lane]; T2 = r2[lane]; T3 = r3[lane]; }
        #pragma unroll
        for (int off = 8; off; off >>= 1) {
            float o1 = __shfl_xor_sync(0xffffffffu, T1, off);
            float o2 = __shfl_xor_sync(0xffffffffu, T2, off);
            float o3 = __shfl_xor_sync(0xffffffffu, T3, off);
            merge3(T1, T2, T3, o1, o2, o3);
        }
        if (lane == 0) { sb[0] = T1; sb[1] = T2; sb[2] = T3; }
    }
    __syncthreads();
    const float M1 = sb[0], M2 = sb[1], M3 = sb[2];
    // M1, M2 are ALWAYS exact (both top-2 elements appear in the pair union);
    // M3 is exact unless one thread owns both M1 and M2 (detected -> fallback).

    // multiplicities + co-location detection (counts also act as barriers)
    int c1   = __syncthreads_count(p1 == M1) + __syncthreads_count(p2 == M1);
    int cW   = __syncthreads_count(p1 == M2) + __syncthreads_count(p2 == M2);
    int both = __syncthreads_count(p1 == M1 && p2 == M2);

    // ---- Bisection (all threads redundantly), exact f32 replication ----
    const float CEXP = (float)(1.0 / 31999.0);          // inv_exp as f32
    const float M1s = 0.5f * M1;                         // Xs = (alpha-1)*X, exact
    const float M2s = 0.5f * M2;
    const float M3s = 0.5f * M3;
    float tmin = M1s - 1.0f;
    float diff = (M1s - (float)0.005590169943749474) - tmin;  // tmax - tmin
    float t    = tmin;
    if (M1s - M2s < 0.98f) {
        // only-M1-above-t => y < 0.98 => powf(y,c) provably < 1: mask == (M2s > t)
        #pragma unroll 1
        for (int it = 0; it < 50; it++) {
            diff *= 0.5f;
            t = tmin + diff;
            if (M2s > t) tmin = t;
        }
    } else {
        #pragma unroll 1
        for (int it = 0; it < 50; it++) {
            diff *= 0.5f;
            t = tmin + diff;
            if ((M2s > t) || (powf(M1s - t, CEXP) >= 1.0f)) tmin = t;
        }
    }
    const float tf = t;               // final Z uses the LAST iteration's t
    const bool needW = (M2s > tf);

    // closed form provably exact iff: M1 unique, M2 unique, M1/M2 in different
    // threads (so M3 is the true 3rd max), and no 3rd element above tf
    const bool fallback = (c1 != 1) || (cW != 1) || (both != 0) || (M3s > tf);

    float S = 0.0f, A = 0.0f, D = 0.0f;
    if (fallback) {
        // ---- rare exact path: full rescan (L2-hot), float4 skip test ----
        // NOTE: tf is always correct here because M1/M2 are always exact.
        const float tf2 = 2.0f * tf;
        float s = 0.0f, a = 0.0f, d = 0.0f;
        #pragma unroll 2
        for (int i = tid; i < V4; i += NT) {
            float4 v = __ldg(&g4[i]);
            float vm = fmaxf(fmaxf(v.x, v.y), fmaxf(v.z, v.w));
            if (vm > tf2) {
                float y;
                y = 0.5f * v.x - tf;
                if (y > 0.0f) { float z = powf(y, CEXP); s += z; a += z * sqrtf(z); d += z * v.x; }
                y = 0.5f * v.y - tf;
                if (y > 0.0f) { float z = powf(y, CEXP); s += z; a += z * sqrtf(z); d += z * v.y; }
                y = 0.5f * v.z - tf;
                if (y > 0.0f) { float z = powf(y, CEXP); s += z; a += z * sqrtf(z); d += z * v.z; }
                y = 0.5f * v.w - tf;
                if (y > 0.0f) { float z = powf(y, CEXP); s += z; a += z * sqrtf(z); d += z * v.w; }
            }
        }
        #pragma unroll
        for (int off = 16; off; off >>= 1) {
            s += __shfl_down_sync(0xffffffffu, s, off);
            a += __shfl_down_sync(0xffffffffu, a, off);
            d += __shfl_down_sync(0xffffffffu, d, off);
        }
        __syncthreads();
        if (lane == 0) { r1[wid] = s; r2[wid] = a; r3[wid] = d; }
        __syncthreads();
        if (tid == 0) {
            #pragma unroll
            for (int w = 0; w < NW; w++) { S += r1[w]; A += r2[w]; D += r3[w]; }
        }
    } else if (tid == 0) {
        // ---- closed form: contributors are exactly {M1} (+ {M2} if needW) ----
        float z1 = powf(M1s - tf, CEXP);
        S = z1; A = z1 * sqrtf(z1); D = z1 * M1;
        if (needW) {
            float z2 = powf(M2s - tf, CEXP);
            S += z2; A += z2 * sqrtf(z2); D += z2 * M2;
        }
    }

    if (tid == 0) {
        // ---- dtype-agnostic target fetch (int32 vs int64 buffer) ----
        // int64 LE with values in [0,32000) => odd 32-bit words are all zero.
        int acc = __ldg(&target_raw[1]) | __ldg(&target_raw[3])
                | __ldg(&target_raw[5]) | __ldg(&target_raw[7])
                | __ldg(&target_raw[9]) | __ldg(&target_raw[11])
                | __ldg(&target_raw[13]) | __ldg(&target_raw[15]);
        int tg = (acc == 0) ? __ldg(&target_raw[2 * (int)row])
                            : __ldg(&target_raw[(int)row]);
        if (tg < 0) tg = 0;
        if (tg >= V) tg = V - 1;   // defensive clamp: never fault

        float xt = __ldg(&xrow[tg]);
        // sum(p^alpha) = A / S^1.5 ; loss = (1 - sumPa)/0.75 + D/S - X[target]
        float sumPa = A / (S * sqrtf(S));
        out[row] = (1.0f - sumPa) / 0.75f + D / S - xt;
    }
}

extern "C" void kernel_launch(void* const* d_in, const int* in_sizes, int n_in,
                              void* d_out, int out_size)
{
    const float* X   = (const float*)d_in[0];
    const int*   tgt = (const int*)d_in[1];
    float*       out = (float*)d_out;
    const int B = out_size;   // 4096 rows

    bisection_loss_kernel<<<B, NT>>>(X, tgt, out);
}